// round 6
// baseline (speedup 1.0000x reference)
#include <cuda_runtime.h>
#include <cuda_fp16.h>
#include <math.h>

// ---------------------------------------------------------------------------
// SiamFC head, round 5.
//   H[b,r,j,p] = sum_{c,q} x'[b,c,r-8,j+q-8] * z'[b,c,p,q]   (HMMA fp16)
//   out[b,i,j] = 0.001 * sum_p H[b,i+p,j,p]
// corr: 2 rows/CTA, A-fragments via single LDG.128 from fragment-ordered ZA.
// prep_x: division-free, register-sliding 8-px strips.
// ---------------------------------------------------------------------------

__device__ __align__(16) unsigned XG[64 * 64 * 112 * 56];     // x' fp16 half2 words
__device__ __align__(16) unsigned ZA[(64 * 64 + 2) * 128];    // z' in A-frag order (+pad)
__device__ __align__(16) float Hbuf[64 * 112 * 16 * 112];     // H[b][r][p][j]

__device__ __forceinline__ float gelu_exact(float v) {
    return 0.5f * v * (1.0f + erff(v * 0.70710678118654752f));
}

// ---- Kernel A: preprocess x -> XG ---------------------------------------------
__global__ __launch_bounds__(192) void prep_x(const float* __restrict__ x,
                                              const float* __restrict__ wx,
                                              const float* __restrict__ bx) {
    int bc = blockIdx.x;        // b*64 + c
    int c  = bc & 63;
    int tid = threadIdx.x;
    __shared__ __align__(16) float sp[98 * 100];

    // zero halo (vectorized full clear)
    float4 z4 = make_float4(0.f, 0.f, 0.f, 0.f);
    for (int i = tid; i < 2450; i += 192) reinterpret_cast<float4*>(sp)[i] = z4;
    __syncthreads();

    // load 96x96 plane: tid -> (row parity, col); no divisions
    {
        int col = (tid < 96) ? tid : tid - 96;
        int rp  = (tid < 96) ? 0 : 1;
        const float* xp = x + (size_t)bc * 9216;
        for (int k = 0; k < 48; ++k) {
            int r = 2 * k + rp;
            sp[(r + 1) * 100 + (col + 1)] = xp[r * 96 + col];
        }
    }
    __syncthreads();

    float w[9];
#pragma unroll
    for (int k = 0; k < 9; ++k) w[k] = __ldg(wx + c * 9 + k);
    float bias = __ldg(bx + c);

    int v4 = tid % 12;          // col group (8 px), one div per thread
    int r0 = tid / 12;          // 0..15
    int xc0 = v4 * 8;

    uint4* dst = reinterpret_cast<uint4*>(XG + (size_t)bc * (112 * 56));
#pragma unroll 1
    for (int it = 0; it < 6; ++it) {
        int r = r0 + 16 * it;   // x row 0..95
        float rowv[3][12];
#pragma unroll
        for (int di = 0; di < 3; ++di) {
            const float4* src = reinterpret_cast<const float4*>(sp + (r + di) * 100 + xc0);
            float4 A = src[0], B = src[1], C = src[2];
            rowv[di][0] = A.x; rowv[di][1] = A.y; rowv[di][2]  = A.z; rowv[di][3]  = A.w;
            rowv[di][4] = B.x; rowv[di][5] = B.y; rowv[di][6]  = B.z; rowv[di][7]  = B.w;
            rowv[di][8] = C.x; rowv[di][9] = C.y; rowv[di][10] = C.z; rowv[di][11] = C.w;
        }
        unsigned ow[4];
#pragma unroll
        for (int t = 0; t < 4; ++t) {
            float f[2];
#pragma unroll
            for (int u = 0; u < 2; ++u) {
                int e = 2 * t + u;  // px within strip
                float conv = bias;
#pragma unroll
                for (int di = 0; di < 3; ++di)
#pragma unroll
                    for (int dj = 0; dj < 3; ++dj)
                        conv = fmaf(w[di * 3 + dj], rowv[di][e + dj], conv);
                f[u] = gelu_exact(rowv[1][e + 1] + conv);
            }
            __half2 h = __floats2half2_rn(f[0], f[1]);
            ow[t] = *reinterpret_cast<unsigned*>(&h);
        }
        dst[(r + 8) * 14 + 1 + v4] = make_uint4(ow[0], ow[1], ow[2], ow[3]);
    }
}

// ---- Kernel B: preprocess z -> ZA (A-fragment order) ---------------------------
__global__ __launch_bounds__(256) void prep_z(const float* __restrict__ z,
                                              const float* __restrict__ wz,
                                              const float* __restrict__ bz) {
    int bc = blockIdx.x;
    int c  = bc & 63;
    __shared__ float sp[18 * 18];

    for (int i = threadIdx.x; i < 18 * 18; i += 256) sp[i] = 0.0f;
    __syncthreads();

    int t = threadIdx.x;
    int p = t >> 4, q = t & 15;
    sp[(p + 1) * 18 + (q + 1)] = z[(size_t)bc * 256 + t];
    __syncthreads();

    float conv = __ldg(bz + c);
#pragma unroll
    for (int di = 0; di < 3; ++di)
#pragma unroll
        for (int dj = 0; dj < 3; ++dj)
            conv = fmaf(__ldg(wz + c * 9 + di * 3 + dj), sp[(p + di) * 18 + (q + dj)], conv);
    float val = gelu_exact(sp[(p + 1) * 18 + (q + 1)] + conv);

    // A-fragment placement for mma.m16n8k16 row-major A
    int lane = ((p & 7) << 2) | ((q & 7) >> 1);
    int reg  = ((p >> 3) & 1) | (((q >> 3) & 1) << 1);
    int h    = q & 1;
    reinterpret_cast<__half*>(ZA)[((size_t)bc * 32 + lane) * 8 + reg * 2 + h] =
        __float2half(val);
}

// ---- Kernel C: correlation GEMM, 2 rows/CTA ------------------------------------
// Grid (48, 64): rows r=8+2bx, r+1. 4 warps; warp w owns j-tiles {w,w+4,w+8,w+12}<13.
// Dynamic smem: 2 rows x (even 4096 + 16 pad + odd 4096) = 16416 words.
#define ROWW 8208
#define ODDO 4112
__global__ __launch_bounds__(128) void corr() {
    extern __shared__ unsigned sq[];
    int r = 8 + 2 * blockIdx.x, b = blockIdx.y;
    int tid = threadIdx.x, lane = tid & 31, w = tid >> 5;

    // Stage even copies (uint4), zero-fill words 56..63
    for (int t = tid; t < 2048; t += 128) {
        int rr = t >> 10, g = t & 1023, c = g >> 4, v = g & 15;
        uint4 d = make_uint4(0u, 0u, 0u, 0u);
        if (v < 14)
            d = __ldg(reinterpret_cast<const uint4*>(
                    XG + (size_t)(b * 64 + c) * 6272 + (size_t)(r + rr) * 56) + v);
        reinterpret_cast<uint4*>(sq)[rr * 2052 + (c << 4) + v] = d;
    }
    __syncthreads();
    // Build odd-shifted copies (uint4 + funnel shifts)
    for (int t = tid; t < 2048; t += 128) {
        int rr = t >> 10, g = t & 1023;
        int ebase = rr * ROWW + (g << 2);
        uint4 e = *reinterpret_cast<const uint4*>(sq + ebase);
        unsigned e4 = sq[ebase + 4];
        uint4 o;
        o.x = __funnelshift_r(e.x, e.y, 16);
        o.y = __funnelshift_r(e.y, e.z, 16);
        o.z = __funnelshift_r(e.z, e.w, 16);
        o.w = __funnelshift_r(e.w, e4, 16);
        reinterpret_cast<uint4*>(sq)[rr * 2052 + 1028 + g] = o;
    }
    __syncthreads();

    // Per-lane B-fragment base (within c-block)
    int nj = lane >> 2;
    int q0 = (lane & 3) << 1;
    int widx = (nj + q0) >> 1;
    const unsigned* e0 = sq + ((nj & 1) ? ODDO : 0) + widx + (w << 2);
    const unsigned* e1 = e0 + ROWW;

    const uint4* zp = reinterpret_cast<const uint4*>(ZA) + (size_t)b * 64 * 32 + lane;

    float acc[2][4][4];
#pragma unroll
    for (int rr = 0; rr < 2; ++rr)
#pragma unroll
        for (int u = 0; u < 4; ++u)
#pragma unroll
            for (int k = 0; k < 4; ++k) acc[rr][u][k] = 0.0f;

    uint4 a = __ldg(zp);
#pragma unroll 1
    for (int c = 0; c < 64; ++c) {
        uint4 an = __ldg(zp + (c + 1) * 32);   // ZA padded: safe at c=63
#pragma unroll
        for (int u = 0; u < 4; ++u) {
            if (w + 4 * u < 13) {
                unsigned b00 = e0[u * 16], b01 = e0[u * 16 + 4];
                asm volatile(
                    "mma.sync.aligned.m16n8k16.row.col.f32.f16.f16.f32 "
                    "{%0,%1,%2,%3}, {%4,%5,%6,%7}, {%8,%9}, {%0,%1,%2,%3};"
                    : "+f"(acc[0][u][0]), "+f"(acc[0][u][1]),
                      "+f"(acc[0][u][2]), "+f"(acc[0][u][3])
                    : "r"(a.x), "r"(a.y), "r"(a.z), "r"(a.w), "r"(b00), "r"(b01));
                unsigned b10 = e1[u * 16], b11 = e1[u * 16 + 4];
                asm volatile(
                    "mma.sync.aligned.m16n8k16.row.col.f32.f16.f16.f32 "
                    "{%0,%1,%2,%3}, {%4,%5,%6,%7}, {%8,%9}, {%0,%1,%2,%3};"
                    : "+f"(acc[1][u][0]), "+f"(acc[1][u][1]),
                      "+f"(acc[1][u][2]), "+f"(acc[1][u][3])
                    : "r"(a.x), "r"(a.y), "r"(a.z), "r"(a.w), "r"(b10), "r"(b11));
            }
        }
        a = an;
        e0 += 64; e1 += 64;
    }

    // Store H for both rows
    int p0 = lane >> 2, jn = (lane & 3) << 1;
#pragma unroll
    for (int rr = 0; rr < 2; ++rr) {
        float* Hb = Hbuf + (size_t)(b * 112 + r + rr) * (16 * 112);
#pragma unroll
        for (int u = 0; u < 4; ++u) {
            int jt = w + 4 * u;
            if (jt < 13) {
                int j = jt * 8 + jn;
                *reinterpret_cast<float2*>(Hb + p0 * 112 + j) =
                    make_float2(acc[rr][u][0], acc[rr][u][1]);
                *reinterpret_cast<float2*>(Hb + (p0 + 8) * 112 + j) =
                    make_float2(acc[rr][u][2], acc[rr][u][3]);
            }
        }
    }
}

// ---- Kernel D: shift-add epilogue -----------------------------------------------
__global__ __launch_bounds__(256) void epilogue(float* __restrict__ out) {
    int t = blockIdx.x * 256 + threadIdx.x;
    if (t >= 64 * 97 * 97) return;
    int b = t / 9409, rem = t - b * 9409;
    int i = rem / 97, j = rem - i * 97;
    const float* Hb = Hbuf + (size_t)b * (112 * 16 * 112);
    float s = 0.0f;
#pragma unroll
    for (int p = 0; p < 16; ++p)
        s += Hb[(size_t)((i + p) * 16 + p) * 112 + j];
    out[t] = s * 0.001f;
}

// ---- launch -----------------------------------------------------------------------
extern "C" void kernel_launch(void* const* d_in, const int* in_sizes, int n_in,
                              void* d_out, int out_size) {
    const float* z  = (const float*)d_in[0];
    const float* x  = (const float*)d_in[1];
    const float* wz = (const float*)d_in[2];
    const float* bz = (const float*)d_in[3];
    const float* wx = (const float*)d_in[4];
    const float* bx = (const float*)d_in[5];
    float* out = (float*)d_out;

    static int smem_set = 0;
    const int SMEM = 2 * ROWW * 4;  // 65664 bytes
    if (!smem_set) {
        cudaFuncSetAttribute(corr, cudaFuncAttributeMaxDynamicSharedMemorySize, SMEM);
        smem_set = 1;
    }

    prep_x<<<4096, 192>>>(x, wx, bx);
    prep_z<<<4096, 256>>>(z, wz, bz);
    corr<<<dim3(48, 64), 128, SMEM>>>();
    epilogue<<<(64 * 97 * 97 + 255) / 256, 256>>>(out);
}

// round 8
// speedup vs baseline: 1.1048x; 1.1048x over previous
#include <cuda_runtime.h>
#include <cuda_fp16.h>
#include <math.h>

// ---------------------------------------------------------------------------
// SiamFC head, round 8: HMMA with f16 accumulators (fp32 flush every 4 c),
// fast-erf GELU in preprocessing.
//   H[b,r,j,p] = sum_{c,q} x'[b,c,r-8,j+q-8] * z'[b,c,p,q]
//   out[b,i,j] = 0.001 * sum_p H[b,i+p,j,p]
// ---------------------------------------------------------------------------

__device__ __align__(16) unsigned XG[64 * 64 * 112 * 56];     // x' fp16 half2 words
__device__ __align__(16) unsigned ZA[(64 * 64 + 2) * 128];    // z' in A-frag order (+pad)
__device__ __align__(16) float Hbuf[64 * 112 * 16 * 112];     // H[b][r][p][j]

// Fast exact-GELU: erf via Abramowitz-Stegun 7.1.26 (|err| <= 1.5e-7 abs).
__device__ __forceinline__ float gelu_fast(float v) {
    float s = fabsf(v) * 0.70710678118654752f;
    float t = __frcp_rn(fmaf(0.3275911f, s, 1.0f));
    float p = fmaf(1.061405429f, t, -1.453152027f);
    p = fmaf(p, t, 1.421413741f);
    p = fmaf(p, t, -0.284496736f);
    p = fmaf(p, t, 0.254829592f);
    p = p * t;
    float erfabs = fmaf(-p, __expf(-s * s), 1.0f);
    float erfs = copysignf(erfabs, v);
    return 0.5f * v * (1.0f + erfs);
}

// ---- Kernel A: preprocess x -> XG ---------------------------------------------
__global__ __launch_bounds__(192) void prep_x(const float* __restrict__ x,
                                              const float* __restrict__ wx,
                                              const float* __restrict__ bx) {
    int bc = blockIdx.x;        // b*64 + c
    int c  = bc & 63;
    int tid = threadIdx.x;
    __shared__ __align__(16) float sp[98 * 100];

    float4 z4 = make_float4(0.f, 0.f, 0.f, 0.f);
    for (int i = tid; i < 2450; i += 192) reinterpret_cast<float4*>(sp)[i] = z4;
    __syncthreads();

    {
        int col = (tid < 96) ? tid : tid - 96;
        int rp  = (tid < 96) ? 0 : 1;
        const float* xp = x + (size_t)bc * 9216;
        for (int k = 0; k < 48; ++k) {
            int r = 2 * k + rp;
            sp[(r + 1) * 100 + (col + 1)] = xp[r * 96 + col];
        }
    }
    __syncthreads();

    float w[9];
#pragma unroll
    for (int k = 0; k < 9; ++k) w[k] = __ldg(wx + c * 9 + k);
    float bias = __ldg(bx + c);

    int v4 = tid % 12;          // col group (8 px)
    int r0 = tid / 12;          // 0..15
    int xc0 = v4 * 8;

    uint4* dst = reinterpret_cast<uint4*>(XG + (size_t)bc * (112 * 56));
#pragma unroll 1
    for (int it = 0; it < 6; ++it) {
        int r = r0 + 16 * it;   // x row 0..95
        float rowv[3][12];
#pragma unroll
        for (int di = 0; di < 3; ++di) {
            const float4* src = reinterpret_cast<const float4*>(sp + (r + di) * 100 + xc0);
            float4 A = src[0], B = src[1], C = src[2];
            rowv[di][0] = A.x; rowv[di][1] = A.y; rowv[di][2]  = A.z; rowv[di][3]  = A.w;
            rowv[di][4] = B.x; rowv[di][5] = B.y; rowv[di][6]  = B.z; rowv[di][7]  = B.w;
            rowv[di][8] = C.x; rowv[di][9] = C.y; rowv[di][10] = C.z; rowv[di][11] = C.w;
        }
        unsigned ow[4];
#pragma unroll
        for (int t = 0; t < 4; ++t) {
            float f[2];
#pragma unroll
            for (int u = 0; u < 2; ++u) {
                int e = 2 * t + u;
                float conv = bias;
#pragma unroll
                for (int di = 0; di < 3; ++di)
#pragma unroll
                    for (int dj = 0; dj < 3; ++dj)
                        conv = fmaf(w[di * 3 + dj], rowv[di][e + dj], conv);
                f[u] = gelu_fast(rowv[1][e + 1] + conv);
            }
            __half2 h = __floats2half2_rn(f[0], f[1]);
            ow[t] = *reinterpret_cast<unsigned*>(&h);
        }
        dst[(r + 8) * 14 + 1 + v4] = make_uint4(ow[0], ow[1], ow[2], ow[3]);
    }
}

// ---- Kernel B: preprocess z -> ZA (A-fragment order) ---------------------------
__global__ __launch_bounds__(256) void prep_z(const float* __restrict__ z,
                                              const float* __restrict__ wz,
                                              const float* __restrict__ bz) {
    int bc = blockIdx.x;
    int c  = bc & 63;
    __shared__ float sp[18 * 18];

    for (int i = threadIdx.x; i < 18 * 18; i += 256) sp[i] = 0.0f;
    __syncthreads();

    int t = threadIdx.x;
    int p = t >> 4, q = t & 15;
    sp[(p + 1) * 18 + (q + 1)] = z[(size_t)bc * 256 + t];
    __syncthreads();

    float conv = __ldg(bz + c);
#pragma unroll
    for (int di = 0; di < 3; ++di)
#pragma unroll
        for (int dj = 0; dj < 3; ++dj)
            conv = fmaf(__ldg(wz + c * 9 + di * 3 + dj), sp[(p + di) * 18 + (q + dj)], conv);
    float val = gelu_fast(sp[(p + 1) * 18 + (q + 1)] + conv);

    int lane = ((p & 7) << 2) | ((q & 7) >> 1);
    int reg  = ((p >> 3) & 1) | (((q >> 3) & 1) << 1);
    int h    = q & 1;
    reinterpret_cast<__half*>(ZA)[((size_t)bc * 32 + lane) * 8 + reg * 2 + h] =
        __float2half(val);
}

// ---- Kernel C: correlation GEMM, 2 rows/CTA, f16 accumulators ------------------
// Grid (48, 64): rows r=8+2bx, r+1. 4 warps; warp w owns j-tiles {w,w+4,w+8,w+12}<13.
#define ROWW 8208
#define ODDO 4112
__global__ __launch_bounds__(128) void corr() {
    extern __shared__ unsigned sq[];
    int r = 8 + 2 * blockIdx.x, b = blockIdx.y;
    int tid = threadIdx.x, lane = tid & 31, w = tid >> 5;

    // Stage even copies (uint4), zero-fill words 56..63
    for (int t = tid; t < 2048; t += 128) {
        int rr = t >> 10, g = t & 1023, c = g >> 4, v = g & 15;
        uint4 d = make_uint4(0u, 0u, 0u, 0u);
        if (v < 14)
            d = __ldg(reinterpret_cast<const uint4*>(
                    XG + (size_t)(b * 64 + c) * 6272 + (size_t)(r + rr) * 56) + v);
        reinterpret_cast<uint4*>(sq)[rr * 2052 + (c << 4) + v] = d;
    }
    __syncthreads();
    // Odd-shifted copies
    for (int t = tid; t < 2048; t += 128) {
        int rr = t >> 10, g = t & 1023;
        int ebase = rr * ROWW + (g << 2);
        uint4 e = *reinterpret_cast<const uint4*>(sq + ebase);
        unsigned e4 = sq[ebase + 4];
        uint4 o;
        o.x = __funnelshift_r(e.x, e.y, 16);
        o.y = __funnelshift_r(e.y, e.z, 16);
        o.z = __funnelshift_r(e.z, e.w, 16);
        o.w = __funnelshift_r(e.w, e4, 16);
        reinterpret_cast<uint4*>(sq)[rr * 2052 + 1028 + g] = o;
    }
    __syncthreads();

    int nj = lane >> 2;
    int q0 = (lane & 3) << 1;
    int widx = (nj + q0) >> 1;
    const unsigned* e0 = sq + ((nj & 1) ? ODDO : 0) + widx + (w << 2);
    const unsigned* e1 = e0 + ROWW;

    const uint4* zp = reinterpret_cast<const uint4*>(ZA) + (size_t)b * 64 * 32 + lane;

    float facc[2][4][4];
#pragma unroll
    for (int rr = 0; rr < 2; ++rr)
#pragma unroll
        for (int u = 0; u < 4; ++u)
#pragma unroll
            for (int k = 0; k < 4; ++k) facc[rr][u][k] = 0.0f;

    unsigned hacc[2][4][2];
#pragma unroll
    for (int rr = 0; rr < 2; ++rr)
#pragma unroll
        for (int u = 0; u < 4; ++u) { hacc[rr][u][0] = 0u; hacc[rr][u][1] = 0u; }

    uint4 a = __ldg(zp);
#pragma unroll 1
    for (int cb = 0; cb < 16; ++cb) {   // 16 blocks of 4 c
#pragma unroll
        for (int ci = 0; ci < 4; ++ci) {
            int c = 4 * cb + ci;
            uint4 an = __ldg(zp + (c + 1) * 32);   // ZA padded: safe at c=63
            const unsigned* p0 = e0 + (c << 6);
            const unsigned* p1 = e1 + (c << 6);
#pragma unroll
            for (int u = 0; u < 4; ++u) {
                if (w + 4 * u < 13) {
                    unsigned b00 = p0[u * 16], b01 = p0[u * 16 + 4];
                    asm volatile(
                        "mma.sync.aligned.m16n8k16.row.col.f16.f16.f16.f16 "
                        "{%0,%1}, {%2,%3,%4,%5}, {%6,%7}, {%0,%1};"
                        : "+r"(hacc[0][u][0]), "+r"(hacc[0][u][1])
                        : "r"(a.x), "r"(a.y), "r"(a.z), "r"(a.w), "r"(b00), "r"(b01));
                    unsigned b10 = p1[u * 16], b11 = p1[u * 16 + 4];
                    asm volatile(
                        "mma.sync.aligned.m16n8k16.row.col.f16.f16.f16.f16 "
                        "{%0,%1}, {%2,%3,%4,%5}, {%6,%7}, {%0,%1};"
                        : "+r"(hacc[1][u][0]), "+r"(hacc[1][u][1])
                        : "r"(a.x), "r"(a.y), "r"(a.z), "r"(a.w), "r"(b10), "r"(b11));
                }
            }
            a = an;
        }
        // Flush f16 fragments into fp32 accumulators, reset fragments
#pragma unroll
        for (int rr = 0; rr < 2; ++rr)
#pragma unroll
            for (int u = 0; u < 4; ++u) {
                __half2 h0 = *reinterpret_cast<__half2*>(&hacc[rr][u][0]);
                __half2 h1 = *reinterpret_cast<__half2*>(&hacc[rr][u][1]);
                float2 f0 = __half22float2(h0);
                float2 f1 = __half22float2(h1);
                facc[rr][u][0] += f0.x; facc[rr][u][1] += f0.y;
                facc[rr][u][2] += f1.x; facc[rr][u][3] += f1.y;
                hacc[rr][u][0] = 0u; hacc[rr][u][1] = 0u;
            }
    }

    // Store H for both rows
    int p0i = lane >> 2, jn = (lane & 3) << 1;
#pragma unroll
    for (int rr = 0; rr < 2; ++rr) {
        float* Hb = Hbuf + (size_t)(b * 112 + r + rr) * (16 * 112);
#pragma unroll
        for (int u = 0; u < 4; ++u) {
            int jt = w + 4 * u;
            if (jt < 13) {
                int j = jt * 8 + jn;
                *reinterpret_cast<float2*>(Hb + p0i * 112 + j) =
                    make_float2(facc[rr][u][0], facc[rr][u][1]);
                *reinterpret_cast<float2*>(Hb + (p0i + 8) * 112 + j) =
                    make_float2(facc[rr][u][2], facc[rr][u][3]);
            }
        }
    }
}

// ---- Kernel D: shift-add epilogue -----------------------------------------------
__global__ __launch_bounds__(256) void epilogue(float* __restrict__ out) {
    int t = blockIdx.x * 256 + threadIdx.x;
    if (t >= 64 * 97 * 97) return;
    int b = t / 9409, rem = t - b * 9409;
    int i = rem / 97, j = rem - i * 97;
    const float* Hb = Hbuf + (size_t)b * (112 * 16 * 112);
    float s = 0.0f;
#pragma unroll
    for (int p = 0; p < 16; ++p)
        s += Hb[(size_t)((i + p) * 16 + p) * 112 + j];
    out[t] = s * 0.001f;
}

// ---- launch -----------------------------------------------------------------------
extern "C" void kernel_launch(void* const* d_in, const int* in_sizes, int n_in,
                              void* d_out, int out_size) {
    const float* z  = (const float*)d_in[0];
    const float* x  = (const float*)d_in[1];
    const float* wz = (const float*)d_in[2];
    const float* bz = (const float*)d_in[3];
    const float* wx = (const float*)d_in[4];
    const float* bx = (const float*)d_in[5];
    float* out = (float*)d_out;

    const int SMEM = 2 * ROWW * 4;  // 65664 bytes
    cudaFuncSetAttribute(corr, cudaFuncAttributeMaxDynamicSharedMemorySize, SMEM);

    prep_x<<<4096, 192>>>(x, wx, bx);
    prep_z<<<4096, 256>>>(z, wz, bz);
    corr<<<dim3(48, 64), 128, SMEM>>>();
    epilogue<<<(64 * 97 * 97 + 255) / 256, 256>>>(out);
}

// round 10
// speedup vs baseline: 1.6554x; 1.4984x over previous
#include <cuda_runtime.h>
#include <cuda_fp16.h>
#include <math.h>

// ---------------------------------------------------------------------------
// SiamFC head, round 10 (round 9 + plane-stride fix).
//   H[b,r,j,p] = sum_{c,q} x'[b,c,r-8,j+q-8] * z'[b,c,p,q]   (HMMA f16-acc)
//   out[b,i,j] = 0.001 * sum_p H[b,i+p,j,p]                  (fused via RED)
// corr: 4 rows/CTA (warp = row), single-copy smem + funnel-shift B-frags,
// epilogue fused with red.global.add.f32 into zero-initialized out.
// ---------------------------------------------------------------------------

__device__ __align__(16) unsigned XG[64 * 64 * 112 * 56];     // x' fp16 half2 words
__device__ __align__(16) unsigned ZA[(64 * 64 + 2) * 128];    // z' in A-frag order (+pad)

// Fast exact-GELU: erf via Abramowitz-Stegun 7.1.26 (|err| <= 1.5e-7 abs).
__device__ __forceinline__ float gelu_fast(float v) {
    float s = fabsf(v) * 0.70710678118654752f;
    float t = __frcp_rn(fmaf(0.3275911f, s, 1.0f));
    float p = fmaf(1.061405429f, t, -1.453152027f);
    p = fmaf(p, t, 1.421413741f);
    p = fmaf(p, t, -0.284496736f);
    p = fmaf(p, t, 0.254829592f);
    p = p * t;
    float erfabs = fmaf(-p, __expf(-s * s), 1.0f);
    float erfs = copysignf(erfabs, v);
    return 0.5f * v * (1.0f + erfs);
}

__device__ __forceinline__ void red_add(float* p, float v) {
    asm volatile("red.global.add.f32 [%0], %1;" :: "l"(p), "f"(v) : "memory");
}

// ---- Kernel A: preprocess x -> XG ---------------------------------------------
__global__ __launch_bounds__(192) void prep_x(const float* __restrict__ x,
                                              const float* __restrict__ wx,
                                              const float* __restrict__ bx) {
    int bc = blockIdx.x;        // b*64 + c
    int c  = bc & 63;
    int tid = threadIdx.x;
    __shared__ __align__(16) float sp[98 * 100];

    float4 z4 = make_float4(0.f, 0.f, 0.f, 0.f);
    for (int i = tid; i < 2450; i += 192) reinterpret_cast<float4*>(sp)[i] = z4;
    __syncthreads();

    {
        int col = (tid < 96) ? tid : tid - 96;
        int rp  = (tid < 96) ? 0 : 1;
        const float* xp = x + (size_t)bc * 9216;
        for (int k = 0; k < 48; ++k) {
            int r = 2 * k + rp;
            sp[(r + 1) * 100 + (col + 1)] = xp[r * 96 + col];
        }
    }
    __syncthreads();

    float w[9];
#pragma unroll
    for (int k = 0; k < 9; ++k) w[k] = __ldg(wx + c * 9 + k);
    float bias = __ldg(bx + c);

    int v4 = tid % 12;
    int r0 = tid / 12;
    int xc0 = v4 * 8;

    uint4* dst = reinterpret_cast<uint4*>(XG + (size_t)bc * (112 * 56));
#pragma unroll 1
    for (int it = 0; it < 6; ++it) {
        int r = r0 + 16 * it;
        float rowv[3][12];
#pragma unroll
        for (int di = 0; di < 3; ++di) {
            const float4* src = reinterpret_cast<const float4*>(sp + (r + di) * 100 + xc0);
            float4 A = src[0], B = src[1], C = src[2];
            rowv[di][0] = A.x; rowv[di][1] = A.y; rowv[di][2]  = A.z; rowv[di][3]  = A.w;
            rowv[di][4] = B.x; rowv[di][5] = B.y; rowv[di][6]  = B.z; rowv[di][7]  = B.w;
            rowv[di][8] = C.x; rowv[di][9] = C.y; rowv[di][10] = C.z; rowv[di][11] = C.w;
        }
        unsigned ow[4];
#pragma unroll
        for (int t = 0; t < 4; ++t) {
            float f[2];
#pragma unroll
            for (int u = 0; u < 2; ++u) {
                int e = 2 * t + u;
                float conv = bias;
#pragma unroll
                for (int di = 0; di < 3; ++di)
#pragma unroll
                    for (int dj = 0; dj < 3; ++dj)
                        conv = fmaf(w[di * 3 + dj], rowv[di][e + dj], conv);
                f[u] = gelu_fast(rowv[1][e + 1] + conv);
            }
            __half2 h = __floats2half2_rn(f[0], f[1]);
            ow[t] = *reinterpret_cast<unsigned*>(&h);
        }
        dst[(r + 8) * 14 + 1 + v4] = make_uint4(ow[0], ow[1], ow[2], ow[3]);
    }
}

// ---- Kernel B: preprocess z -> ZA (A-fragment order) ---------------------------
__global__ __launch_bounds__(256) void prep_z(const float* __restrict__ z,
                                              const float* __restrict__ wz,
                                              const float* __restrict__ bz) {
    int bc = blockIdx.x;
    int c  = bc & 63;
    __shared__ float sp[18 * 18];

    for (int i = threadIdx.x; i < 18 * 18; i += 256) sp[i] = 0.0f;
    __syncthreads();

    int t = threadIdx.x;
    int p = t >> 4, q = t & 15;
    sp[(p + 1) * 18 + (q + 1)] = z[(size_t)bc * 256 + t];
    __syncthreads();

    float conv = __ldg(bz + c);
#pragma unroll
    for (int di = 0; di < 3; ++di)
#pragma unroll
        for (int dj = 0; dj < 3; ++dj)
            conv = fmaf(__ldg(wz + c * 9 + di * 3 + dj), sp[(p + di) * 18 + (q + dj)], conv);
    float val = gelu_fast(sp[(p + 1) * 18 + (q + 1)] + conv);

    int lane = ((p & 7) << 2) | ((q & 7) >> 1);
    int reg  = ((p >> 3) & 1) | (((q >> 3) & 1) << 1);
    int h    = q & 1;
    reinterpret_cast<__half*>(ZA)[((size_t)bc * 32 + lane) * 8 + reg * 2 + h] =
        __float2half(val);
}

// ---- Kernel Z: zero-init out ----------------------------------------------------
__global__ __launch_bounds__(256) void zero_out(float* __restrict__ out, int n4) {
    int t = blockIdx.x * 256 + threadIdx.x;
    float4 z4 = make_float4(0.f, 0.f, 0.f, 0.f);
    if (t < n4) reinterpret_cast<float4*>(out)[t] = z4;
}

// ---- Kernel C: correlation GEMM + fused scatter epilogue ------------------------
// Grid (24, 64): rows r0=8+4bx .. r0+3, warp w handles row r0+w, all 13 j-tiles.
__global__ __launch_bounds__(128) void corr(float* __restrict__ out) {
    extern __shared__ unsigned sq[];   // [row(4)][c(64)][word(64)] = 65536 B
    int r0 = 8 + 4 * blockIdx.x, b = blockIdx.y;
    int tid = threadIdx.x, lane = tid & 31, w = tid >> 5;
    int r = r0 + w;

    // Stage 4 rows: zero-fill words 56..63. Plane = 1568 uint4, row = 14 uint4.
    for (int t = tid; t < 4096; t += 128) {
        int row = t >> 10, g = t & 1023, c = g >> 4, v = g & 15;
        uint4 d = make_uint4(0u, 0u, 0u, 0u);
        if (v < 14)
            d = __ldg(reinterpret_cast<const uint4*>(XG) +
                      (size_t)(b * 64 + c) * 1568 + (size_t)(r0 + row) * 14 + v);
        reinterpret_cast<uint4*>(sq)[t] = d;
    }
    __syncthreads();

    // Per-lane B-frag addressing: element idx = 8*jt + nj + q0 (+1), word = idx>>1
    int nj = lane >> 2;
    int q0 = (lane & 3) << 1;
    int loff = (nj + q0) >> 1;                 // 0..6
    unsigned sh = (unsigned)((nj & 1) << 4);   // funnel shift: 0 or 16
    const unsigned* base_row = sq + (w << 12); // w * 4096 words

    const uint4* zp = reinterpret_cast<const uint4*>(ZA) + (size_t)b * 64 * 32 + lane;

    float facc[13][4];
#pragma unroll
    for (int t = 0; t < 13; ++t)
#pragma unroll
        for (int k = 0; k < 4; ++k) facc[t][k] = 0.0f;

    unsigned hacc[13][2];
#pragma unroll
    for (int t = 0; t < 13; ++t) { hacc[t][0] = 0u; hacc[t][1] = 0u; }

    uint4 a = __ldg(zp);
#pragma unroll 1
    for (int cb = 0; cb < 16; ++cb) {
#pragma unroll
        for (int ci = 0; ci < 4; ++ci) {
            int c = 4 * cb + ci;
            uint4 an = __ldg(zp + (c + 1) * 32);   // ZA padded: safe at c=63
            const unsigned* bc = base_row + (c << 6) + loff;
#pragma unroll
            for (int t = 0; t < 13; ++t) {
                unsigned w0 = bc[4 * t],     w1 = bc[4 * t + 1];
                unsigned w2 = bc[4 * t + 4], w3 = bc[4 * t + 5];
                unsigned b0 = __funnelshift_r(w0, w1, sh);
                unsigned b1 = __funnelshift_r(w2, w3, sh);
                asm volatile(
                    "mma.sync.aligned.m16n8k16.row.col.f16.f16.f16.f16 "
                    "{%0,%1}, {%2,%3,%4,%5}, {%6,%7}, {%0,%1};"
                    : "+r"(hacc[t][0]), "+r"(hacc[t][1])
                    : "r"(a.x), "r"(a.y), "r"(a.z), "r"(a.w), "r"(b0), "r"(b1));
            }
            a = an;
        }
        // Flush f16 fragments into fp32 accumulators
#pragma unroll
        for (int t = 0; t < 13; ++t) {
            __half2 h0 = *reinterpret_cast<__half2*>(&hacc[t][0]);
            __half2 h1 = *reinterpret_cast<__half2*>(&hacc[t][1]);
            float2 f0 = __half22float2(h0);
            float2 f1 = __half22float2(h1);
            facc[t][0] += f0.x; facc[t][1] += f0.y;
            facc[t][2] += f1.x; facc[t][3] += f1.y;
            hacc[t][0] = 0u; hacc[t][1] = 0u;
        }
    }

    // Fused epilogue: out[b, r-p, j] += 0.001 * H[p][j]
    int p0 = lane >> 2, jn = (lane & 3) << 1;
    float* ob = out + (size_t)b * 9409;
    int i_hi = r - p0;        // p = p0      (1..103)
    int i_lo = i_hi - 8;      // p = p0 + 8  (-7..95)
#pragma unroll
    for (int t = 0; t < 13; ++t) {
        int j = t * 8 + jn;
        bool j0 = (j <= 96), j1 = (j < 96);
        if (i_hi <= 96) {
            if (j0) red_add(ob + i_hi * 97 + j,     facc[t][0] * 0.001f);
            if (j1) red_add(ob + i_hi * 97 + j + 1, facc[t][1] * 0.001f);
        }
        if (i_lo >= 0) {
            if (j0) red_add(ob + i_lo * 97 + j,     facc[t][2] * 0.001f);
            if (j1) red_add(ob + i_lo * 97 + j + 1, facc[t][3] * 0.001f);
        }
    }
}

// ---- launch -----------------------------------------------------------------------
extern "C" void kernel_launch(void* const* d_in, const int* in_sizes, int n_in,
                              void* d_out, int out_size) {
    const float* z  = (const float*)d_in[0];
    const float* x  = (const float*)d_in[1];
    const float* wz = (const float*)d_in[2];
    const float* bz = (const float*)d_in[3];
    const float* wx = (const float*)d_in[4];
    const float* bx = (const float*)d_in[5];
    float* out = (float*)d_out;

    const int SMEM = 65536;
    cudaFuncSetAttribute(corr, cudaFuncAttributeMaxDynamicSharedMemorySize, SMEM);

    int n4 = out_size / 4;  // 602176 / 4 = 150544
    zero_out<<<(n4 + 255) / 256, 256>>>(out, n4);
    prep_x<<<4096, 192>>>(x, wx, bx);
    prep_z<<<4096, 256>>>(z, wz, bz);
    corr<<<dim3(24, 64), 128, SMEM>>>(out);
}